// round 6
// baseline (speedup 1.0000x reference)
#include <cuda_runtime.h>
#include <cuda_fp16.h>
#include <cstdint>

#define NN   50000
#define EE   800000
#define DIN  64
#define DH   128
#define DOUT 64

#define WS_STRIDE 136
#define AS_STRIDE 132

// ---------------- scratch (static device globals; no allocation) ----------------
__device__ int    g_is64;
__device__ int    g_cnt[NN];
__device__ int    g_offs[NN + 1];
__device__ int    g_cursor[NN];
__device__ int    g_bsum[64];
__device__ int    g_boff[64];
__device__ int    g_src[EE];
__device__ __half g_xh[(size_t)NN * DIN];     // x in fp16 (gather payload, layer 1)
__device__ float  g_h [(size_t)NN * DH];      // layer-1 output
__device__ __half g_yh[(size_t)NN * DOUT];    // y = h@W2l in fp16 (gather payload, layer 2)
__device__ float  g_z [(size_t)NN * DOUT];    // z = h@W2r + b2 (self term, layer 2)

// ---------------- edge index helpers (int32 vs int64 detection) ----------------
__device__ __forceinline__ int edge_val(const void* ei, int idx) {
    if (g_is64) return (int)((const long long*)ei)[idx];
    return ((const int*)ei)[idx];
}

// zero counters + fp16 convert + dtype detect (single kernel).
// Grid sized for the x conversion: NN*DIN/4 = 800000 threads.
__global__ void k_init(const float* __restrict__ x, const int* __restrict__ ei32) {
    int i = blockIdx.x * blockDim.x + threadIdx.x;
    if (i < (NN * DIN) / 4) {
        float4 v = *reinterpret_cast<const float4*>(x + 4 * i);
        __half2 h0 = __floats2half2_rn(v.x, v.y);
        __half2 h1 = __floats2half2_rn(v.z, v.w);
        uint2 pack;
        pack.x = *reinterpret_cast<uint32_t*>(&h0);
        pack.y = *reinterpret_cast<uint32_t*>(&h1);
        *reinterpret_cast<uint2*>(g_xh + 4 * i) = pack;
    }
    if (i < NN) g_cnt[i] = 0;
    if (i == 0) {
        // int64 little-endian values < 2^31 -> every odd 32-bit word is zero.
        int nz = 0;
        for (int j = 0; j < 128; j++) nz |= ei32[2 * j + 1];
        g_is64 = (nz == 0) ? 1 : 0;
    }
}

// ---------------- CSR build ----------------
__global__ void k_hist(const void* __restrict__ ei) {
    int e = blockIdx.x * blockDim.x + threadIdx.x;
    if (e < EE) {
        int d = edge_val(ei, EE + e);
        atomicAdd(&g_cnt[d], 1);
    }
}

__global__ void k_scan1() {
    __shared__ int s[1024];
    int t = threadIdx.x;
    int gid = blockIdx.x * 1024 + t;
    int v = (gid < NN) ? g_cnt[gid] : 0;
    s[t] = v;
    __syncthreads();
    for (int o = 1; o < 1024; o <<= 1) {
        int x = (t >= o) ? s[t - o] : 0;
        __syncthreads();
        s[t] += x;
        __syncthreads();
    }
    if (gid < NN) g_offs[gid + 1] = s[t];
    if (t == 1023) g_bsum[blockIdx.x] = s[1023];
}

__global__ void k_scan2(int nb) {
    __shared__ int s[64];
    int t = threadIdx.x;
    int v = (t < nb) ? g_bsum[t] : 0;
    s[t] = v;
    __syncthreads();
    for (int o = 1; o < 64; o <<= 1) {
        int x = (t >= o) ? s[t - o] : 0;
        __syncthreads();
        s[t] += x;
        __syncthreads();
    }
    g_boff[t] = s[t] - v;
}

__global__ void k_scan3() {
    int t = threadIdx.x;
    int gid = blockIdx.x * 1024 + t;
    if (gid < NN) {
        int f = g_offs[gid + 1] + g_boff[blockIdx.x];
        g_offs[gid + 1] = f;
        g_cursor[gid] = f - g_cnt[gid];
        if (gid == 0) g_offs[0] = 0;
    }
}

__global__ void k_scatter(const void* __restrict__ ei) {
    int e = blockIdx.x * blockDim.x + threadIdx.x;
    if (e < EE) {
        int s = edge_val(ei, e);
        int d = edge_val(ei, EE + e);
        int pos = atomicAdd(&g_cursor[d], 1);
        g_src[pos] = s;
    }
}

// ---------------- tf32 helpers ----------------
__device__ __forceinline__ uint32_t f2tf(float f) {
    uint32_t u; asm("cvt.rna.tf32.f32 %0, %1;" : "=r"(u) : "f"(f)); return u;
}
__device__ __forceinline__ void mma_tf32(float4& d, const uint32_t* a, const uint32_t* b) {
    asm volatile("mma.sync.aligned.m16n8k8.row.col.f32.tf32.tf32.f32 "
        "{%0,%1,%2,%3}, {%4,%5,%6,%7}, {%8,%9}, {%0,%1,%2,%3};"
        : "+f"(d.x), "+f"(d.y), "+f"(d.z), "+f"(d.w)
        : "r"(a[0]), "r"(a[1]), "r"(a[2]), "r"(a[3]), "r"(b[0]), "r"(b[1]));
}

// ---------------- fp16 gather-sum of one node row (warp-collective, 2 cols/lane) --
__device__ __forceinline__ float2 gather_row_h(const __half* __restrict__ feat,
                                               int node, int lane) {
    int s = g_offs[node], e = g_offs[node + 1];
    float2 a0 = make_float2(0.f, 0.f), a1 = make_float2(0.f, 0.f);
    float2 a2 = make_float2(0.f, 0.f), a3 = make_float2(0.f, 0.f);
    int i = s;
    for (; i + 4 <= e; i += 4) {
        int s0 = __ldg(&g_src[i]),     s1 = __ldg(&g_src[i + 1]);
        int s2 = __ldg(&g_src[i + 2]), s3 = __ldg(&g_src[i + 3]);
        float2 v0 = __half22float2(*reinterpret_cast<const __half2*>(feat + (size_t)s0 * 64 + 2 * lane));
        float2 v1 = __half22float2(*reinterpret_cast<const __half2*>(feat + (size_t)s1 * 64 + 2 * lane));
        float2 v2 = __half22float2(*reinterpret_cast<const __half2*>(feat + (size_t)s2 * 64 + 2 * lane));
        float2 v3 = __half22float2(*reinterpret_cast<const __half2*>(feat + (size_t)s3 * 64 + 2 * lane));
        a0.x += v0.x; a0.y += v0.y;  a1.x += v1.x; a1.y += v1.y;
        a2.x += v2.x; a2.y += v2.y;  a3.x += v3.x; a3.y += v3.y;
    }
    for (; i < e; i++) {
        int sr = __ldg(&g_src[i]);
        float2 v = __half22float2(*reinterpret_cast<const __half2*>(feat + (size_t)sr * 64 + 2 * lane));
        a0.x += v.x; a0.y += v.y;
    }
    return make_float2((a0.x + a1.x) + (a2.x + a3.x),
                       (a0.y + a1.y) + (a2.y + a3.y));
}

// ---------------- layer 1: fused gather + tf32 GEMM + L2norm + BN + ReLU ----------
// h = relu(bn(l2norm([segsum(x[src]) | x] @ [W1l;W1r] + b1)))
__global__ __launch_bounds__(256)
void k_tgemm1(const float* __restrict__ x,
              const float* __restrict__ Wl, const float* __restrict__ Wr,
              const float* __restrict__ bias,
              const float* __restrict__ gam, const float* __restrict__ bet,
              const float* __restrict__ rm,  const float* __restrict__ rv,
              float* __restrict__ out) {
    constexpr int BM = 64, K = 128, NOUT = 128;
    extern __shared__ uint32_t smu[];
    uint32_t* Ws = smu;                       // [K][WS_STRIDE] tf32 bits
    uint32_t* As = smu + K * WS_STRIDE;       // [BM][AS_STRIDE] tf32 bits
    float*    Cs = reinterpret_cast<float*>(As);

    const int tid  = threadIdx.x;
    const int lane = tid & 31, wid = tid >> 5;
    const int g = lane >> 2, t = lane & 3;
    const int wm = wid >> 2, wn = wid & 3;

    // stage W = [W1l;W1r] as tf32 once per CTA
    for (int v = tid; v < K * NOUT / 4; v += 256) {
        int idx = v * 4, k = idx / NOUT, n = idx % NOUT;
        float4 w;
        if (k < 64) w = *reinterpret_cast<const float4*>(Wl + k * NOUT + n);
        else        w = *reinterpret_cast<const float4*>(Wr + (k - 64) * NOUT + n);
        uint32_t* p = Ws + k * WS_STRIDE + n;
        p[0] = f2tf(w.x); p[1] = f2tf(w.y); p[2] = f2tf(w.z); p[3] = f2tf(w.w);
    }

    float4 bv = *reinterpret_cast<const float4*>(bias + 4 * lane);
    float4 G  = *reinterpret_cast<const float4*>(gam  + 4 * lane);
    float4 Bb = *reinterpret_cast<const float4*>(bet  + 4 * lane);
    float4 RM = *reinterpret_cast<const float4*>(rm   + 4 * lane);
    float4 RV = *reinterpret_cast<const float4*>(rv   + 4 * lane);
    float4 IS;
    IS.x = rsqrtf(RV.x + 1e-5f); IS.y = rsqrtf(RV.y + 1e-5f);
    IS.z = rsqrtf(RV.z + 1e-5f); IS.w = rsqrtf(RV.w + 1e-5f);

    const int numTiles = (NN + BM - 1) / BM;
    for (int tile = blockIdx.x; tile < numTiles; tile += gridDim.x) {
        __syncthreads();
        const int base = tile * BM;

        // gather + stage A tile (warp wid handles rows wid*8 .. wid*8+7)
#pragma unroll
        for (int rr = 0; rr < 8; rr++) {
            int row = wid * 8 + rr;
            int node = base + row;
            float2 agg = make_float2(0.f, 0.f);
            float2 self = make_float2(0.f, 0.f);
            if (node < NN) {
                agg  = gather_row_h(g_xh, node, lane);
                self = *reinterpret_cast<const float2*>(x + (size_t)node * 64 + 2 * lane);
            }
            uint32_t* p = As + row * AS_STRIDE;
            p[2 * lane]          = f2tf(agg.x);
            p[2 * lane + 1]      = f2tf(agg.y);
            p[64 + 2 * lane]     = f2tf(self.x);
            p[64 + 2 * lane + 1] = f2tf(self.y);
        }
        __syncthreads();

        float4 acc[2][4];
#pragma unroll
        for (int i = 0; i < 2; i++)
#pragma unroll
            for (int j = 0; j < 4; j++) acc[i][j] = make_float4(0.f, 0.f, 0.f, 0.f);

#pragma unroll 4
        for (int kk = 0; kk < 16; kk++) {
            const int cb = kk * 8;
            uint32_t a[2][4], b[4][2];
#pragma unroll
            for (int i = 0; i < 2; i++) {
                const uint32_t* ap = As + (wm * 32 + i * 16 + g) * AS_STRIDE + cb + t;
                a[i][0] = ap[0];
                a[i][1] = ap[8 * AS_STRIDE];
                a[i][2] = ap[4];
                a[i][3] = ap[8 * AS_STRIDE + 4];
            }
#pragma unroll
            for (int j = 0; j < 4; j++) {
                const uint32_t* bp = Ws + (cb + t) * WS_STRIDE + wn * 32 + j * 8 + g;
                b[j][0] = bp[0];
                b[j][1] = bp[4 * WS_STRIDE];
            }
#pragma unroll
            for (int i = 0; i < 2; i++)
#pragma unroll
                for (int j = 0; j < 4; j++) mma_tf32(acc[i][j], a[i], b[j]);
        }

        __syncthreads();

#pragma unroll
        for (int i = 0; i < 2; i++)
#pragma unroll
            for (int j = 0; j < 4; j++) {
                int row = wm * 32 + i * 16 + g;
                int col = wn * 32 + j * 8 + 2 * t;
                Cs[row * AS_STRIDE + col]           = acc[i][j].x;
                Cs[row * AS_STRIDE + col + 1]       = acc[i][j].y;
                Cs[(row + 8) * AS_STRIDE + col]     = acc[i][j].z;
                Cs[(row + 8) * AS_STRIDE + col + 1] = acc[i][j].w;
            }
        __syncthreads();

#pragma unroll
        for (int rr = 0; rr < 8; rr++) {
            int row = wid * 8 + rr;
            int node = base + row;
            float4 v = *reinterpret_cast<float4*>(Cs + row * AS_STRIDE + 4 * lane);
            v.x += bv.x; v.y += bv.y; v.z += bv.z; v.w += bv.w;
            float ss = v.x * v.x + v.y * v.y + v.z * v.z + v.w * v.w;
#pragma unroll
            for (int o = 16; o > 0; o >>= 1) ss += __shfl_xor_sync(0xffffffffu, ss, o);
            float sc = 1.0f / fmaxf(sqrtf(ss), 1e-12f);
            if (node < NN) {
                float4 o;
                o.x = fmaxf(G.x * (v.x * sc - RM.x) * IS.x + Bb.x, 0.f);
                o.y = fmaxf(G.y * (v.y * sc - RM.y) * IS.y + Bb.y, 0.f);
                o.z = fmaxf(G.z * (v.z * sc - RM.z) * IS.z + Bb.z, 0.f);
                o.w = fmaxf(G.w * (v.w * sc - RM.w) * IS.w + Bb.w, 0.f);
                *reinterpret_cast<float4*>(out + (size_t)node * NOUT + 4 * lane) = o;
            }
        }
    }
}

// ---------------- layer 2 projection: y(fp16) = h@W2l ; z(fp32) = h@W2r + b2 ------
__global__ __launch_bounds__(256)
void k_tgemm2(const float* __restrict__ A,
              const float* __restrict__ Wl, const float* __restrict__ Wr,
              const float* __restrict__ bias) {
    constexpr int BM = 64, K = 128, NOUT = 128;
    extern __shared__ uint32_t smu[];
    uint32_t* Ws = smu;
    uint32_t* As = smu + K * WS_STRIDE;
    float*    Cs = reinterpret_cast<float*>(As);

    const int tid  = threadIdx.x;
    const int lane = tid & 31, wid = tid >> 5;
    const int g = lane >> 2, t = lane & 3;
    const int wm = wid >> 2, wn = wid & 3;

    // Ws[k][n]: n<64 -> W2l[k][n] ; n>=64 -> W2r[k][n-64]
    for (int v = tid; v < K * NOUT / 4; v += 256) {
        int idx = v * 4, k = idx / NOUT, n = idx % NOUT;
        float4 w;
        if (n < 64) w = *reinterpret_cast<const float4*>(Wl + k * 64 + n);
        else        w = *reinterpret_cast<const float4*>(Wr + k * 64 + (n - 64));
        uint32_t* p = Ws + k * WS_STRIDE + n;
        p[0] = f2tf(w.x); p[1] = f2tf(w.y); p[2] = f2tf(w.z); p[3] = f2tf(w.w);
    }

    float4 bv = make_float4(0.f, 0.f, 0.f, 0.f);
    if (4 * lane >= 64) bv = *reinterpret_cast<const float4*>(bias + 4 * lane - 64);

    const int numTiles = (NN + BM - 1) / BM;
    for (int tile = blockIdx.x; tile < numTiles; tile += gridDim.x) {
        __syncthreads();
        const int base = tile * BM;
        for (int v = tid; v < BM * K / 4; v += 256) {
            int idx = v * 4, r = idx / K, c = idx % K;
            int node = base + r;
            float4 a = make_float4(0.f, 0.f, 0.f, 0.f);
            if (node < NN)
                a = *reinterpret_cast<const float4*>(A + (size_t)node * 128 + c);
            uint32_t* p = As + r * AS_STRIDE + c;
            p[0] = f2tf(a.x); p[1] = f2tf(a.y); p[2] = f2tf(a.z); p[3] = f2tf(a.w);
        }
        __syncthreads();

        float4 acc[2][4];
#pragma unroll
        for (int i = 0; i < 2; i++)
#pragma unroll
            for (int j = 0; j < 4; j++) acc[i][j] = make_float4(0.f, 0.f, 0.f, 0.f);

#pragma unroll 4
        for (int kk = 0; kk < 16; kk++) {
            const int cb = kk * 8;
            uint32_t a[2][4], b[4][2];
#pragma unroll
            for (int i = 0; i < 2; i++) {
                const uint32_t* ap = As + (wm * 32 + i * 16 + g) * AS_STRIDE + cb + t;
                a[i][0] = ap[0];
                a[i][1] = ap[8 * AS_STRIDE];
                a[i][2] = ap[4];
                a[i][3] = ap[8 * AS_STRIDE + 4];
            }
#pragma unroll
            for (int j = 0; j < 4; j++) {
                const uint32_t* bp = Ws + (cb + t) * WS_STRIDE + wn * 32 + j * 8 + g;
                b[j][0] = bp[0];
                b[j][1] = bp[4 * WS_STRIDE];
            }
#pragma unroll
            for (int i = 0; i < 2; i++)
#pragma unroll
                for (int j = 0; j < 4; j++) mma_tf32(acc[i][j], a[i], b[j]);
        }

        __syncthreads();

#pragma unroll
        for (int i = 0; i < 2; i++)
#pragma unroll
            for (int j = 0; j < 4; j++) {
                int row = wm * 32 + i * 16 + g;
                int col = wn * 32 + j * 8 + 2 * t;
                Cs[row * AS_STRIDE + col]           = acc[i][j].x;
                Cs[row * AS_STRIDE + col + 1]       = acc[i][j].y;
                Cs[(row + 8) * AS_STRIDE + col]     = acc[i][j].z;
                Cs[(row + 8) * AS_STRIDE + col + 1] = acc[i][j].w;
            }
        __syncthreads();

#pragma unroll
        for (int rr = 0; rr < 8; rr++) {
            int row = wid * 8 + rr;
            int node = base + row;
            if (node >= NN) continue;
            float4 v = *reinterpret_cast<float4*>(Cs + row * AS_STRIDE + 4 * lane);
            if (4 * lane < 64) {
                // y -> fp16
                __half2 h0 = __floats2half2_rn(v.x, v.y);
                __half2 h1 = __floats2half2_rn(v.z, v.w);
                uint2 pack;
                pack.x = *reinterpret_cast<uint32_t*>(&h0);
                pack.y = *reinterpret_cast<uint32_t*>(&h1);
                *reinterpret_cast<uint2*>(g_yh + (size_t)node * 64 + 4 * lane) = pack;
            } else {
                // z -> fp32 (+b2)
                float4 o = make_float4(v.x + bv.x, v.y + bv.y, v.z + bv.z, v.w + bv.w);
                *reinterpret_cast<float4*>(g_z + (size_t)node * 64 + (4 * lane - 64)) = o;
            }
        }
    }
}

// ---------------- layer-2 final: gather y(fp16), add z, L2norm, BN -> out ---------
__global__ void k_final(const float* __restrict__ gam, const float* __restrict__ bet,
                        const float* __restrict__ rm,  const float* __restrict__ rv,
                        float* __restrict__ out) {
    int w = (blockIdx.x * blockDim.x + threadIdx.x) >> 5;
    if (w >= NN) return;
    int lane = threadIdx.x & 31;

    float2 v = gather_row_h(g_yh, w, lane);
    float2 z = *reinterpret_cast<const float2*>(g_z + (size_t)w * 64 + 2 * lane);
    v.x += z.x; v.y += z.y;

    float ss = v.x * v.x + v.y * v.y;
#pragma unroll
    for (int o = 16; o > 0; o >>= 1) ss += __shfl_xor_sync(0xffffffffu, ss, o);
    float scale = 1.0f / fmaxf(sqrtf(ss), 1e-12f);

    float2 G  = *reinterpret_cast<const float2*>(gam + 2 * lane);
    float2 B  = *reinterpret_cast<const float2*>(bet + 2 * lane);
    float2 RM = *reinterpret_cast<const float2*>(rm  + 2 * lane);
    float2 RV = *reinterpret_cast<const float2*>(rv  + 2 * lane);
    float2 o;
    o.x = G.x * (v.x * scale - RM.x) * rsqrtf(RV.x + 1e-5f) + B.x;
    o.y = G.y * (v.y * scale - RM.y) * rsqrtf(RV.y + 1e-5f) + B.y;
    *reinterpret_cast<float2*>(out + (size_t)w * 64 + 2 * lane) = o;
}

// ---------------- launch ----------------
extern "C" void kernel_launch(void* const* d_in, const int* in_sizes, int n_in,
                              void* d_out, int out_size) {
    const float* x    = (const float*)d_in[0];
    const void*  ei   = d_in[1];
    const float* W1l  = (const float*)d_in[2];
    const float* b1   = (const float*)d_in[3];
    const float* W1r  = (const float*)d_in[4];
    const float* gam1 = (const float*)d_in[5];
    const float* bet1 = (const float*)d_in[6];
    const float* rm1  = (const float*)d_in[7];
    const float* rv1  = (const float*)d_in[8];
    const float* W2l  = (const float*)d_in[9];
    const float* b2   = (const float*)d_in[10];
    const float* W2r  = (const float*)d_in[11];
    const float* gam2 = (const float*)d_in[12];
    const float* bet2 = (const float*)d_in[13];
    const float* rm2  = (const float*)d_in[14];
    const float* rv2  = (const float*)d_in[15];
    float* out = (float*)d_out;

    float* h;
    cudaGetSymbolAddress((void**)&h, g_h);

    constexpr int SMEM = (128 * WS_STRIDE + 64 * AS_STRIDE) * 4;   // 103,424 B
    cudaFuncSetAttribute(k_tgemm1, cudaFuncAttributeMaxDynamicSharedMemorySize, SMEM);
    cudaFuncSetAttribute(k_tgemm2, cudaFuncAttributeMaxDynamicSharedMemorySize, SMEM);

    const int NB = (NN + 1023) / 1024;
    const int EB = (EE + 255) / 256;
    const int WARP_BLOCKS = (NN * 32 + 255) / 256;

    // init (zero counters + x->fp16 + dtype detect), then CSR build
    k_init<<<((NN * DIN) / 4 + 255) / 256, 256>>>(x, (const int*)ei);
    k_hist<<<EB, 256>>>(ei);
    k_scan1<<<NB, 1024>>>();
    k_scan2<<<1, 64>>>(NB);
    k_scan3<<<NB, 1024>>>();
    k_scatter<<<EB, 256>>>(ei);

    // layer 1: fused gather + tensor GEMM + norm/BN/ReLU
    k_tgemm1<<<296, 256, SMEM>>>(x, W1l, W1r, b1, gam1, bet1, rm1, rv1, h);

    // layer 2: projection GEMM (y fp16, z fp32) -> gather+add+norm+BN
    k_tgemm2<<<296, 256, SMEM>>>(h, W2l, W2r, b2);
    k_final<<<WARP_BLOCKS, 256>>>(gam2, bet2, rm2, rv2, out);
}

// round 7
// speedup vs baseline: 1.0570x; 1.0570x over previous
#include <cuda_runtime.h>
#include <cuda_fp16.h>
#include <cstdint>

#define NN   50000
#define EE   800000
#define DIN  64
#define DH   128
#define DOUT 64

#define WS_STRIDE 136
#define AS_STRIDE 132

// ---------------- scratch (static device globals; no allocation) ----------------
__device__ int    g_is64;
__device__ int    g_cnt[NN];
__device__ int    g_offs[NN + 1];
__device__ int    g_cursor[NN];
__device__ int    g_bsum[64];
__device__ int    g_boff[64];
__device__ int    g_src[EE];
__device__ __half g_xh[(size_t)NN * DIN];     // x in fp16 (gather payload, layer 1)
__device__ float  g_agg1[(size_t)NN * DIN];   // segsum(x[src]) fp32
__device__ float  g_h [(size_t)NN * DH];      // layer-1 output
__device__ __half g_yh[(size_t)NN * DOUT];    // y = h@W2l in fp16 (gather payload, layer 2)
__device__ float  g_z [(size_t)NN * DOUT];    // z = h@W2r + b2 (self term, layer 2)

// ---------------- edge index helpers (int32 vs int64 detection) ----------------
__device__ __forceinline__ int edge_val(const void* ei, int idx) {
    if (g_is64) return (int)((const long long*)ei)[idx];
    return ((const int*)ei)[idx];
}

// zero counters + fp16 convert + dtype detect (single kernel).
__global__ void k_init(const float* __restrict__ x, const int* __restrict__ ei32) {
    int i = blockIdx.x * blockDim.x + threadIdx.x;
    if (i < (NN * DIN) / 4) {
        float4 v = *reinterpret_cast<const float4*>(x + 4 * i);
        __half2 h0 = __floats2half2_rn(v.x, v.y);
        __half2 h1 = __floats2half2_rn(v.z, v.w);
        uint2 pack;
        pack.x = *reinterpret_cast<uint32_t*>(&h0);
        pack.y = *reinterpret_cast<uint32_t*>(&h1);
        *reinterpret_cast<uint2*>(g_xh + 4 * i) = pack;
    }
    if (i < NN) g_cnt[i] = 0;
    if (i == 0) {
        int nz = 0;
        for (int j = 0; j < 128; j++) nz |= ei32[2 * j + 1];
        g_is64 = (nz == 0) ? 1 : 0;
    }
}

// ---------------- CSR build ----------------
__global__ void k_hist(const void* __restrict__ ei) {
    int e = blockIdx.x * blockDim.x + threadIdx.x;
    if (e < EE) {
        int d = edge_val(ei, EE + e);
        atomicAdd(&g_cnt[d], 1);
    }
}

__global__ void k_scan1() {
    __shared__ int s[1024];
    int t = threadIdx.x;
    int gid = blockIdx.x * 1024 + t;
    int v = (gid < NN) ? g_cnt[gid] : 0;
    s[t] = v;
    __syncthreads();
    for (int o = 1; o < 1024; o <<= 1) {
        int x = (t >= o) ? s[t - o] : 0;
        __syncthreads();
        s[t] += x;
        __syncthreads();
    }
    if (gid < NN) g_offs[gid + 1] = s[t];
    if (t == 1023) g_bsum[blockIdx.x] = s[1023];
}

__global__ void k_scan2(int nb) {
    __shared__ int s[64];
    int t = threadIdx.x;
    int v = (t < nb) ? g_bsum[t] : 0;
    s[t] = v;
    __syncthreads();
    for (int o = 1; o < 64; o <<= 1) {
        int x = (t >= o) ? s[t - o] : 0;
        __syncthreads();
        s[t] += x;
        __syncthreads();
    }
    g_boff[t] = s[t] - v;
}

__global__ void k_scan3() {
    int t = threadIdx.x;
    int gid = blockIdx.x * 1024 + t;
    if (gid < NN) {
        int f = g_offs[gid + 1] + g_boff[blockIdx.x];
        g_offs[gid + 1] = f;
        g_cursor[gid] = f - g_cnt[gid];
        if (gid == 0) g_offs[0] = 0;
    }
}

__global__ void k_scatter(const void* __restrict__ ei) {
    int e = blockIdx.x * blockDim.x + threadIdx.x;
    if (e < EE) {
        int s = edge_val(ei, e);
        int d = edge_val(ei, EE + e);
        int pos = atomicAdd(&g_cursor[d], 1);
        g_src[pos] = s;
    }
}

// ---------------- fp16 gather-sum of one node row (warp-collective, 2 cols/lane) --
__device__ __forceinline__ float2 gather_row_h(const __half* __restrict__ feat,
                                               int node, int lane) {
    int s = g_offs[node], e = g_offs[node + 1];
    float2 a0 = make_float2(0.f, 0.f), a1 = make_float2(0.f, 0.f);
    float2 a2 = make_float2(0.f, 0.f), a3 = make_float2(0.f, 0.f);
    int i = s;
    for (; i + 4 <= e; i += 4) {
        int s0 = __ldg(&g_src[i]),     s1 = __ldg(&g_src[i + 1]);
        int s2 = __ldg(&g_src[i + 2]), s3 = __ldg(&g_src[i + 3]);
        float2 v0 = __half22float2(*reinterpret_cast<const __half2*>(feat + (size_t)s0 * 64 + 2 * lane));
        float2 v1 = __half22float2(*reinterpret_cast<const __half2*>(feat + (size_t)s1 * 64 + 2 * lane));
        float2 v2 = __half22float2(*reinterpret_cast<const __half2*>(feat + (size_t)s2 * 64 + 2 * lane));
        float2 v3 = __half22float2(*reinterpret_cast<const __half2*>(feat + (size_t)s3 * 64 + 2 * lane));
        a0.x += v0.x; a0.y += v0.y;  a1.x += v1.x; a1.y += v1.y;
        a2.x += v2.x; a2.y += v2.y;  a3.x += v3.x; a3.y += v3.y;
    }
    for (; i < e; i++) {
        int sr = __ldg(&g_src[i]);
        float2 v = __half22float2(*reinterpret_cast<const __half2*>(feat + (size_t)sr * 64 + 2 * lane));
        a0.x += v.x; a0.y += v.y;
    }
    return make_float2((a0.x + a1.x) + (a2.x + a3.x),
                       (a0.y + a1.y) + (a2.y + a3.y));
}

// ---------------- layer-1 aggregation: agg1 = segsum(xh[src]) (warp per node) -----
__global__ void k_agg1(float* __restrict__ out) {
    int w = (blockIdx.x * blockDim.x + threadIdx.x) >> 5;
    if (w >= NN) return;
    int lane = threadIdx.x & 31;
    float2 acc = gather_row_h(g_xh, w, lane);
    *reinterpret_cast<float2*>(out + (size_t)w * 64 + 2 * lane) = acc;
}

// ---------------- tf32 helpers ----------------
__device__ __forceinline__ uint32_t f2tf(float f) {
    uint32_t u; asm("cvt.rna.tf32.f32 %0, %1;" : "=r"(u) : "f"(f)); return u;
}
__device__ __forceinline__ void mma_tf32(float4& d, const uint32_t* a, const uint32_t* b) {
    asm volatile("mma.sync.aligned.m16n8k8.row.col.f32.tf32.tf32.f32 "
        "{%0,%1,%2,%3}, {%4,%5,%6,%7}, {%8,%9}, {%0,%1,%2,%3};"
        : "+f"(d.x), "+f"(d.y), "+f"(d.z), "+f"(d.w)
        : "r"(a[0]), "r"(a[1]), "r"(a[2]), "r"(a[3]), "r"(b[0]), "r"(b[1]));
}

// ---------------- layer 1: tf32 GEMM + L2norm + BN + ReLU -------------------------
// h = relu(bn(l2norm([agg1|x] @ [W1l;W1r] + b1)))
__global__ __launch_bounds__(256)
void k_tgemm1(const float* __restrict__ A1, const float* __restrict__ A2,
              const float* __restrict__ Wl, const float* __restrict__ Wr,
              const float* __restrict__ bias,
              const float* __restrict__ gam, const float* __restrict__ bet,
              const float* __restrict__ rm,  const float* __restrict__ rv,
              float* __restrict__ out) {
    constexpr int BM = 64, K = 128, NOUT = 128;
    extern __shared__ uint32_t smu[];
    uint32_t* Ws = smu;                       // [K][WS_STRIDE] tf32 bits
    uint32_t* As = smu + K * WS_STRIDE;       // [BM][AS_STRIDE] tf32 bits
    float*    Cs = reinterpret_cast<float*>(As);

    const int tid  = threadIdx.x;
    const int lane = tid & 31, wid = tid >> 5;
    const int g = lane >> 2, t = lane & 3;
    const int wm = wid >> 2, wn = wid & 3;

    for (int v = tid; v < K * NOUT / 4; v += 256) {
        int idx = v * 4, k = idx / NOUT, n = idx % NOUT;
        float4 w;
        if (k < 64) w = *reinterpret_cast<const float4*>(Wl + k * NOUT + n);
        else        w = *reinterpret_cast<const float4*>(Wr + (k - 64) * NOUT + n);
        uint32_t* p = Ws + k * WS_STRIDE + n;
        p[0] = f2tf(w.x); p[1] = f2tf(w.y); p[2] = f2tf(w.z); p[3] = f2tf(w.w);
    }

    float4 bv = *reinterpret_cast<const float4*>(bias + 4 * lane);
    float4 G  = *reinterpret_cast<const float4*>(gam  + 4 * lane);
    float4 Bb = *reinterpret_cast<const float4*>(bet  + 4 * lane);
    float4 RM = *reinterpret_cast<const float4*>(rm   + 4 * lane);
    float4 RV = *reinterpret_cast<const float4*>(rv   + 4 * lane);
    float4 IS;
    IS.x = rsqrtf(RV.x + 1e-5f); IS.y = rsqrtf(RV.y + 1e-5f);
    IS.z = rsqrtf(RV.z + 1e-5f); IS.w = rsqrtf(RV.w + 1e-5f);

    const int numTiles = (NN + BM - 1) / BM;
    for (int tile = blockIdx.x; tile < numTiles; tile += gridDim.x) {
        __syncthreads();
        const int base = tile * BM;

        for (int v = tid; v < BM * K / 4; v += 256) {
            int idx = v * 4, r = idx / K, c = idx % K;
            int node = base + r;
            float4 a = make_float4(0.f, 0.f, 0.f, 0.f);
            if (node < NN) {
                if (c < 64) a = *reinterpret_cast<const float4*>(A1 + (size_t)node * 64 + c);
                else        a = *reinterpret_cast<const float4*>(A2 + (size_t)node * 64 + (c - 64));
            }
            uint32_t* p = As + r * AS_STRIDE + c;
            p[0] = f2tf(a.x); p[1] = f2tf(a.y); p[2] = f2tf(a.z); p[3] = f2tf(a.w);
        }
        __syncthreads();

        float4 acc[2][4];
#pragma unroll
        for (int i = 0; i < 2; i++)
#pragma unroll
            for (int j = 0; j < 4; j++) acc[i][j] = make_float4(0.f, 0.f, 0.f, 0.f);

#pragma unroll 4
        for (int kk = 0; kk < 16; kk++) {
            const int cb = kk * 8;
            uint32_t a[2][4], b[4][2];
#pragma unroll
            for (int i = 0; i < 2; i++) {
                const uint32_t* ap = As + (wm * 32 + i * 16 + g) * AS_STRIDE + cb + t;
                a[i][0] = ap[0];
                a[i][1] = ap[8 * AS_STRIDE];
                a[i][2] = ap[4];
                a[i][3] = ap[8 * AS_STRIDE + 4];
            }
#pragma unroll
            for (int j = 0; j < 4; j++) {
                const uint32_t* bp = Ws + (cb + t) * WS_STRIDE + wn * 32 + j * 8 + g;
                b[j][0] = bp[0];
                b[j][1] = bp[4 * WS_STRIDE];
            }
#pragma unroll
            for (int i = 0; i < 2; i++)
#pragma unroll
                for (int j = 0; j < 4; j++) mma_tf32(acc[i][j], a[i], b[j]);
        }

        __syncthreads();

#pragma unroll
        for (int i = 0; i < 2; i++)
#pragma unroll
            for (int j = 0; j < 4; j++) {
                int row = wm * 32 + i * 16 + g;
                int col = wn * 32 + j * 8 + 2 * t;
                Cs[row * AS_STRIDE + col]           = acc[i][j].x;
                Cs[row * AS_STRIDE + col + 1]       = acc[i][j].y;
                Cs[(row + 8) * AS_STRIDE + col]     = acc[i][j].z;
                Cs[(row + 8) * AS_STRIDE + col + 1] = acc[i][j].w;
            }
        __syncthreads();

#pragma unroll
        for (int rr = 0; rr < 8; rr++) {
            int row = wid * 8 + rr;
            int node = base + row;
            float4 v = *reinterpret_cast<float4*>(Cs + row * AS_STRIDE + 4 * lane);
            v.x += bv.x; v.y += bv.y; v.z += bv.z; v.w += bv.w;
            float ss = v.x * v.x + v.y * v.y + v.z * v.z + v.w * v.w;
#pragma unroll
            for (int o = 16; o > 0; o >>= 1) ss += __shfl_xor_sync(0xffffffffu, ss, o);
            float sc = 1.0f / fmaxf(sqrtf(ss), 1e-12f);
            if (node < NN) {
                float4 o;
                o.x = fmaxf(G.x * (v.x * sc - RM.x) * IS.x + Bb.x, 0.f);
                o.y = fmaxf(G.y * (v.y * sc - RM.y) * IS.y + Bb.y, 0.f);
                o.z = fmaxf(G.z * (v.z * sc - RM.z) * IS.z + Bb.z, 0.f);
                o.w = fmaxf(G.w * (v.w * sc - RM.w) * IS.w + Bb.w, 0.f);
                *reinterpret_cast<float4*>(out + (size_t)node * NOUT + 4 * lane) = o;
            }
        }
    }
}

// ---------------- layer 2 projection: y(fp16) = h@W2l ; z(fp32) = h@W2r + b2 ------
__global__ __launch_bounds__(256)
void k_tgemm2(const float* __restrict__ A,
              const float* __restrict__ Wl, const float* __restrict__ Wr,
              const float* __restrict__ bias) {
    constexpr int BM = 64, K = 128, NOUT = 128;
    extern __shared__ uint32_t smu[];
    uint32_t* Ws = smu;
    uint32_t* As = smu + K * WS_STRIDE;
    float*    Cs = reinterpret_cast<float*>(As);

    const int tid  = threadIdx.x;
    const int lane = tid & 31, wid = tid >> 5;
    const int g = lane >> 2, t = lane & 3;
    const int wm = wid >> 2, wn = wid & 3;

    for (int v = tid; v < K * NOUT / 4; v += 256) {
        int idx = v * 4, k = idx / NOUT, n = idx % NOUT;
        float4 w;
        if (n < 64) w = *reinterpret_cast<const float4*>(Wl + k * 64 + n);
        else        w = *reinterpret_cast<const float4*>(Wr + k * 64 + (n - 64));
        uint32_t* p = Ws + k * WS_STRIDE + n;
        p[0] = f2tf(w.x); p[1] = f2tf(w.y); p[2] = f2tf(w.z); p[3] = f2tf(w.w);
    }

    float4 bv = make_float4(0.f, 0.f, 0.f, 0.f);
    if (4 * lane >= 64) bv = *reinterpret_cast<const float4*>(bias + 4 * lane - 64);

    const int numTiles = (NN + BM - 1) / BM;
    for (int tile = blockIdx.x; tile < numTiles; tile += gridDim.x) {
        __syncthreads();
        const int base = tile * BM;
        for (int v = tid; v < BM * K / 4; v += 256) {
            int idx = v * 4, r = idx / K, c = idx % K;
            int node = base + r;
            float4 a = make_float4(0.f, 0.f, 0.f, 0.f);
            if (node < NN)
                a = *reinterpret_cast<const float4*>(A + (size_t)node * 128 + c);
            uint32_t* p = As + r * AS_STRIDE + c;
            p[0] = f2tf(a.x); p[1] = f2tf(a.y); p[2] = f2tf(a.z); p[3] = f2tf(a.w);
        }
        __syncthreads();

        float4 acc[2][4];
#pragma unroll
        for (int i = 0; i < 2; i++)
#pragma unroll
            for (int j = 0; j < 4; j++) acc[i][j] = make_float4(0.f, 0.f, 0.f, 0.f);

#pragma unroll 4
        for (int kk = 0; kk < 16; kk++) {
            const int cb = kk * 8;
            uint32_t a[2][4], b[4][2];
#pragma unroll
            for (int i = 0; i < 2; i++) {
                const uint32_t* ap = As + (wm * 32 + i * 16 + g) * AS_STRIDE + cb + t;
                a[i][0] = ap[0];
                a[i][1] = ap[8 * AS_STRIDE];
                a[i][2] = ap[4];
                a[i][3] = ap[8 * AS_STRIDE + 4];
            }
#pragma unroll
            for (int j = 0; j < 4; j++) {
                const uint32_t* bp = Ws + (cb + t) * WS_STRIDE + wn * 32 + j * 8 + g;
                b[j][0] = bp[0];
                b[j][1] = bp[4 * WS_STRIDE];
            }
#pragma unroll
            for (int i = 0; i < 2; i++)
#pragma unroll
                for (int j = 0; j < 4; j++) mma_tf32(acc[i][j], a[i], b[j]);
        }

        __syncthreads();

#pragma unroll
        for (int i = 0; i < 2; i++)
#pragma unroll
            for (int j = 0; j < 4; j++) {
                int row = wm * 32 + i * 16 + g;
                int col = wn * 32 + j * 8 + 2 * t;
                Cs[row * AS_STRIDE + col]           = acc[i][j].x;
                Cs[row * AS_STRIDE + col + 1]       = acc[i][j].y;
                Cs[(row + 8) * AS_STRIDE + col]     = acc[i][j].z;
                Cs[(row + 8) * AS_STRIDE + col + 1] = acc[i][j].w;
            }
        __syncthreads();

#pragma unroll
        for (int rr = 0; rr < 8; rr++) {
            int row = wid * 8 + rr;
            int node = base + row;
            if (node >= NN) continue;
            float4 v = *reinterpret_cast<float4*>(Cs + row * AS_STRIDE + 4 * lane);
            if (4 * lane < 64) {
                __half2 h0 = __floats2half2_rn(v.x, v.y);
                __half2 h1 = __floats2half2_rn(v.z, v.w);
                uint2 pack;
                pack.x = *reinterpret_cast<uint32_t*>(&h0);
                pack.y = *reinterpret_cast<uint32_t*>(&h1);
                *reinterpret_cast<uint2*>(g_yh + (size_t)node * 64 + 4 * lane) = pack;
            } else {
                float4 o = make_float4(v.x + bv.x, v.y + bv.y, v.z + bv.z, v.w + bv.w);
                *reinterpret_cast<float4*>(g_z + (size_t)node * 64 + (4 * lane - 64)) = o;
            }
        }
    }
}

// ---------------- layer-2 final: gather y(fp16), add z, L2norm, BN -> out ---------
__global__ void k_final(const float* __restrict__ gam, const float* __restrict__ bet,
                        const float* __restrict__ rm,  const float* __restrict__ rv,
                        float* __restrict__ out) {
    int w = (blockIdx.x * blockDim.x + threadIdx.x) >> 5;
    if (w >= NN) return;
    int lane = threadIdx.x & 31;

    float2 v = gather_row_h(g_yh, w, lane);
    float2 z = *reinterpret_cast<const float2*>(g_z + (size_t)w * 64 + 2 * lane);
    v.x += z.x; v.y += z.y;

    float ss = v.x * v.x + v.y * v.y;
#pragma unroll
    for (int o = 16; o > 0; o >>= 1) ss += __shfl_xor_sync(0xffffffffu, ss, o);
    float scale = 1.0f / fmaxf(sqrtf(ss), 1e-12f);

    float2 G  = *reinterpret_cast<const float2*>(gam + 2 * lane);
    float2 B  = *reinterpret_cast<const float2*>(bet + 2 * lane);
    float2 RM = *reinterpret_cast<const float2*>(rm  + 2 * lane);
    float2 RV = *reinterpret_cast<const float2*>(rv  + 2 * lane);
    float2 o;
    o.x = G.x * (v.x * scale - RM.x) * rsqrtf(RV.x + 1e-5f) + B.x;
    o.y = G.y * (v.y * scale - RM.y) * rsqrtf(RV.y + 1e-5f) + B.y;
    *reinterpret_cast<float2*>(out + (size_t)w * 64 + 2 * lane) = o;
}

// ---------------- launch ----------------
extern "C" void kernel_launch(void* const* d_in, const int* in_sizes, int n_in,
                              void* d_out, int out_size) {
    const float* x    = (const float*)d_in[0];
    const void*  ei   = d_in[1];
    const float* W1l  = (const float*)d_in[2];
    const float* b1   = (const float*)d_in[3];
    const float* W1r  = (const float*)d_in[4];
    const float* gam1 = (const float*)d_in[5];
    const float* bet1 = (const float*)d_in[6];
    const float* rm1  = (const float*)d_in[7];
    const float* rv1  = (const float*)d_in[8];
    const float* W2l  = (const float*)d_in[9];
    const float* b2   = (const float*)d_in[10];
    const float* W2r  = (const float*)d_in[11];
    const float* gam2 = (const float*)d_in[12];
    const float* bet2 = (const float*)d_in[13];
    const float* rm2  = (const float*)d_in[14];
    const float* rv2  = (const float*)d_in[15];
    float* out = (float*)d_out;

    float *agg1, *h;
    cudaGetSymbolAddress((void**)&agg1, g_agg1);
    cudaGetSymbolAddress((void**)&h,    g_h);

    constexpr int SMEM = (128 * WS_STRIDE + 64 * AS_STRIDE) * 4;   // 103,424 B
    cudaFuncSetAttribute(k_tgemm1, cudaFuncAttributeMaxDynamicSharedMemorySize, SMEM);
    cudaFuncSetAttribute(k_tgemm2, cudaFuncAttributeMaxDynamicSharedMemorySize, SMEM);

    const int NB = (NN + 1023) / 1024;
    const int EB = (EE + 255) / 256;
    const int WARP_BLOCKS = (NN * 32 + 255) / 256;

    // init (zero counters + x->fp16 + dtype detect), then CSR build
    k_init<<<((NN * DIN) / 4 + 255) / 256, 256>>>(x, (const int*)ei);
    k_hist<<<EB, 256>>>(ei);
    k_scan1<<<NB, 1024>>>();
    k_scan2<<<1, 64>>>(NB);
    k_scan3<<<NB, 1024>>>();
    k_scatter<<<EB, 256>>>(ei);

    // layer 1: high-parallelism fp16 gather -> tf32 GEMM + fused norm/BN/ReLU
    k_agg1<<<WARP_BLOCKS, 256>>>(agg1);
    k_tgemm1<<<296, 256, SMEM>>>(agg1, x, W1l, W1r, b1, gam1, bet1, rm1, rv1, h);

    // layer 2: projection GEMM (y fp16, z fp32) -> fp16 gather + add + norm + BN
    k_tgemm2<<<296, 256, SMEM>>>(h, W2l, W2r, b2);
    k_final<<<WARP_BLOCKS, 256>>>(gam2, bet2, rm2, rv2, out);
}